// round 1
// baseline (speedup 1.0000x reference)
#include <cuda_runtime.h>

#define N_USERS   50000
#define N_ITEMS   30000
#define N_ENT     100000
#define N_REL     50
#define N_EDGES   1500000
#define N_INTER   1000000
#define D         64
#define GAMMA_F   0.1f

// ---------------- static device scratch (no allocations allowed) ----------------
__device__ int   g_bins[N_ENT];
__device__ int   g_cursor[N_ENT];
__device__ int   g_eoff[N_ENT + 1];
__device__ int   g_roff[N_USERS + 1];
__device__ int   g_coff[N_ITEMS + 1];
__device__ int   g_stail[N_EDGES];
__device__ int   g_srel[N_EDGES];
__device__ int   g_rcol[N_INTER];
__device__ int   g_ridx[N_INTER];
__device__ int   g_crow[N_INTER];
__device__ float g_wkg[N_ITEMS * D];     // rel_i * item_kg, precomputed per item
__device__ float g_uA[N_USERS * D];
__device__ float g_uB[N_USERS * D];
__device__ float g_cA[N_USERS * D];
__device__ float g_cB[N_USERS * D];
__device__ float g_pe[N_INTER];
__device__ float g_pcfe[N_INTER];

// ---------------- small utility kernels ----------------
__global__ void zero_bins_kernel(int n) {
    int i = blockIdx.x * blockDim.x + threadIdx.x;
    if (i < n) g_bins[i] = 0;
}

__global__ void hist_kernel(const int* __restrict__ keys, int n, int stride) {
    int i = blockIdx.x * blockDim.x + threadIdx.x;
    if (i < n) atomicAdd(&g_bins[keys[(size_t)i * stride]], 1);
}

// single-block exclusive scan over g_bins -> offs (+cursor copy). which: 0=eoff,1=roff,2=coff
__global__ void scan_kernel(int n, int which) {
    int* offs = (which == 0) ? g_eoff : (which == 1) ? g_roff : g_coff;
    __shared__ int warpsum[32];
    __shared__ int s_carry;
    int tid = threadIdx.x, lane = tid & 31, wid = tid >> 5;
    if (tid == 0) s_carry = 0;
    __syncthreads();
    for (int base = 0; base < n; base += 1024) {
        int i = base + tid;
        int v = (i < n) ? g_bins[i] : 0;
        int x = v;
        #pragma unroll
        for (int o = 1; o < 32; o <<= 1) {
            int t = __shfl_up_sync(0xffffffffu, x, o);
            if (lane >= o) x += t;
        }
        if (lane == 31) warpsum[wid] = x;
        __syncthreads();
        if (wid == 0) {
            int w = warpsum[lane];
            #pragma unroll
            for (int o = 1; o < 32; o <<= 1) {
                int t = __shfl_up_sync(0xffffffffu, w, o);
                if (lane >= o) w += t;
            }
            warpsum[lane] = w;
        }
        __syncthreads();
        int incl = x + (wid ? warpsum[wid - 1] : 0);
        int carry = s_carry;
        if (i < n) {
            int off = carry + incl - v;
            offs[i] = off;
            g_cursor[i] = off;
        }
        __syncthreads();
        if (tid == 1023) s_carry = carry + incl;
        __syncthreads();
    }
    if (threadIdx.x == 0) offs[n] = s_carry;
}

__global__ void scatter_edges_kernel(const int* __restrict__ head,
                                     const int* __restrict__ tail,
                                     const int* __restrict__ etype, int n) {
    int e = blockIdx.x * blockDim.x + threadIdx.x;
    if (e < n) {
        int h = head[e];
        int pos = atomicAdd(&g_cursor[h], 1);
        g_stail[pos] = tail[e];
        g_srel[pos]  = etype[e];
    }
}

__global__ void scatter_inter_row_kernel(const int* __restrict__ imat, int n) {
    int j = blockIdx.x * blockDim.x + threadIdx.x;
    if (j < n) {
        int r = imat[(size_t)2 * j];
        int c = imat[(size_t)2 * j + 1];
        int pos = atomicAdd(&g_cursor[r], 1);
        g_rcol[pos] = c;
        g_ridx[pos] = j;
    }
}

__global__ void scatter_inter_col_kernel(const int* __restrict__ imat, int n) {
    int j = blockIdx.x * blockDim.x + threadIdx.x;
    if (j < n) {
        int r = imat[(size_t)2 * j];
        int c = imat[(size_t)2 * j + 1];
        int pos = atomicAdd(&g_cursor[c], 1);
        g_crow[pos] = r;
    }
}

// ---------------- KG aggregation: warp per entity, fused matmuls ----------------
__global__ void __launch_bounds__(256) entity_kernel(
    const float* __restrict__ ent, const float* __restrict__ relw,
    const float* __restrict__ W1, const float* __restrict__ b1,
    const float* __restrict__ W2, const float* __restrict__ b2,
    float* __restrict__ out_agg)
{
    __shared__ float sW1t[D * D];          // transposed: [k][d]
    __shared__ float sW2t[D * D];
    __shared__ float sRel[N_REL * D];
    __shared__ float sMean[8][D];
    int tid = threadIdx.x;
    for (int i = tid; i < D * D; i += 256) {
        int d = i / D, k = i % D;
        sW1t[k * D + d] = W1[i];
        sW2t[k * D + d] = W2[i];
    }
    for (int i = tid; i < N_REL * D; i += 256) sRel[i] = relw[i];
    __syncthreads();

    int warp = tid >> 5, lane = tid & 31;
    int h = blockIdx.x * 8 + warp;
    if (h >= N_ENT) return;
    int s = g_eoff[h], e = g_eoff[h + 1];
    bool head_item = (h < N_ITEMS);

    float2 a1 = make_float2(0.f, 0.f), a2 = a1, ar = a1;
    int c1 = 0, c2 = 0;
    for (int j = s; j < e; j++) {
        int t = g_stail[j];
        int r = g_srel[j];
        float2 te = *(const float2*)&ent[(size_t)t * D + 2 * lane];
        float2 re = *(const float2*)&sRel[r * D + 2 * lane];
        ar.x += re.x; ar.y += re.y;
        bool cross = head_item ^ (t < N_ITEMS);
        if (cross) { a1.x += te.x * re.x; a1.y += te.y * re.y; c1++; }
        else       { a2.x += te.x + re.x; a2.y += te.y + re.y; c2++; }
    }
    float inv1 = 1.f / fmaxf((float)c1, 1.f);
    float inv2 = 1.f / fmaxf((float)c2, 1.f);
    float invr = 1.f / fmaxf((float)(e - s), 1.f);
    a1.x *= inv1; a1.y *= inv1;
    a2.x *= inv2; a2.y *= inv2;
    ar.x *= invr; ar.y *= invr;

    // wkg = rel_mean * original item embedding (items only)
    if (head_item) {
        float2 kg = *(const float2*)&ent[(size_t)h * D + 2 * lane];
        float2 w  = make_float2(ar.x * kg.x, ar.y * kg.y);
        *(float2*)&g_wkg[(size_t)h * D + 2 * lane] = w;
    }

    // agg1 @ W1^T + b1 -> lrelu -> /2
    sMean[warp][2 * lane] = a1.x;
    sMean[warp][2 * lane + 1] = a1.y;
    __syncwarp();
    float o0 = b1[2 * lane], o1 = b1[2 * lane + 1];
    #pragma unroll 8
    for (int k = 0; k < D; k++) {
        float m = sMean[warp][k];
        float2 w = *(const float2*)&sW1t[k * D + 2 * lane];
        o0 += m * w.x; o1 += m * w.y;
    }
    o0 = (o0 >= 0.f ? o0 : 0.01f * o0) * 0.5f;
    o1 = (o1 >= 0.f ? o1 : 0.01f * o1) * 0.5f;
    __syncwarp();

    // agg2 @ W2^T + b2 -> lrelu -> /2
    sMean[warp][2 * lane] = a2.x;
    sMean[warp][2 * lane + 1] = a2.y;
    __syncwarp();
    float p0 = b2[2 * lane], p1 = b2[2 * lane + 1];
    #pragma unroll 8
    for (int k = 0; k < D; k++) {
        float m = sMean[warp][k];
        float2 w = *(const float2*)&sW2t[k * D + 2 * lane];
        p0 += m * w.x; p1 += m * w.y;
    }
    p0 = (p0 >= 0.f ? p0 : 0.01f * p0) * 0.5f;
    p1 = (p1 >= 0.f ? p1 : 0.01f * p1) * 0.5f;

    float2 o = make_float2(o0 + p0, o1 + p1);
    *(float2*)&out_agg[(size_t)h * D + 2 * lane] = o;
}

// ---------------- CF attention iteration: warp per user, no atomics ----------------
__global__ void __launch_bounds__(256) iter_kernel(
    const float* __restrict__ uin0, const float* __restrict__ cin0, int in_sel,
    float* __restrict__ uout0, float* __restrict__ cout0, int out_sel,
    const float* __restrict__ ent, const float* __restrict__ icf,
    float* __restrict__ mask_out, int last)
{
    const float* uin = (in_sel == 0) ? uin0 : (in_sel == 1) ? g_uA : g_uB;
    const float* cin = (in_sel == 0) ? cin0 : (in_sel == 1) ? g_cA : g_cB;
    float* uout = (out_sel == 0) ? g_uA : (out_sel == 1) ? g_uB : uout0;
    float* cout = (out_sel == 0) ? g_cA : (out_sel == 1) ? g_cB : cout0;

    int gw = (blockIdx.x * 256 + threadIdx.x) >> 5;
    int lane = threadIdx.x & 31;
    if (gw >= N_USERS) return;
    int s = g_roff[gw], e = g_roff[gw + 1];

    float2 u = *(const float2*)&uin[(size_t)gw * D + 2 * lane];
    float2 c = *(const float2*)&cin[(size_t)gw * D + 2 * lane];

    float z = 0.f, zc = 0.f;
    for (int j = s; j < e; j++) {
        int col = g_rcol[j];
        float2 w = *(const float2*)&g_wkg[(size_t)col * D + 2 * lane];
        float2 v = *(const float2*)&icf[(size_t)col * D + 2 * lane];
        float d1 = u.x * w.x + u.y * w.y;
        float d2 = c.x * v.x + c.y * v.y;
        #pragma unroll
        for (int o = 16; o; o >>= 1) {
            d1 += __shfl_xor_sync(0xffffffffu, d1, o);
            d2 += __shfl_xor_sync(0xffffffffu, d2, o);
        }
        float p  = 1.f / (1.f + __expf(-d1));   // sigmoid
        float q  = 1.f / (1.f + __expf(-d2));
        float ep = __expf(p);                   // softmax numerator (p in (0,1): safe)
        float eq = __expf(q);
        z += ep; zc += eq;
        if (lane == 0) { g_pe[j] = ep; g_pcfe[j] = eq; }
    }

    float iz  = (z  > 0.f) ? 1.f / z  : 0.f;
    float izc = (zc > 0.f) ? 1.f / zc : 0.f;
    float2 au = make_float2(0.f, 0.f), ac = make_float2(0.f, 0.f);
    for (int j = s; j < e; j++) {
        int col = g_rcol[j];
        float pn = g_pe[j] * iz;
        float qn = g_pcfe[j] * izc;
        float sp = 1.f / (1.f + __expf(-pn));
        float sq = 1.f / (1.f + __expf(-qn));
        float m  = (fabsf(sp - sq) < GAMMA_F) ? 1.f : 0.f;
        if (last && lane == 0) mask_out[g_ridx[j]] = m;
        float cu = pn * m, cc = qn * m;
        float2 kg = *(const float2*)&ent[(size_t)col * D + 2 * lane];
        float2 v  = *(const float2*)&icf[(size_t)col * D + 2 * lane];
        au.x += cu * kg.x; au.y += cu * kg.y;
        ac.x += cc * v.x;  ac.y += cc * v.y;
    }

    if (!last) {
        float su = au.x * au.x + au.y * au.y;
        float sc = ac.x * ac.x + ac.y * ac.y;
        #pragma unroll
        for (int o = 16; o; o >>= 1) {
            su += __shfl_xor_sync(0xffffffffu, su, o);
            sc += __shfl_xor_sync(0xffffffffu, sc, o);
        }
        float nu = fmaxf(sqrtf(su), 1e-12f);
        float nc = fmaxf(sqrtf(sc), 1e-12f);
        au.x /= nu; au.y /= nu;
        ac.x /= nc; ac.y /= nc;
    }
    *(float2*)&uout[(size_t)gw * D + 2 * lane] = au;
    *(float2*)&cout[(size_t)gw * D + 2 * lane] = ac;
}

// ---------------- item_agg: warp per item ----------------
__global__ void __launch_bounds__(256) item_kernel(
    const float* __restrict__ ucf, float* __restrict__ out_item)
{
    int gw = (blockIdx.x * 256 + threadIdx.x) >> 5;
    int lane = threadIdx.x & 31;
    if (gw >= N_ITEMS) return;
    int s = g_coff[gw], e = g_coff[gw + 1];
    float2 acc = make_float2(0.f, 0.f);
    for (int j = s; j < e; j++) {
        int r = g_crow[j];
        float2 v = *(const float2*)&ucf[(size_t)r * D + 2 * lane];
        acc.x += v.x; acc.y += v.y;
    }
    float inv = 1.f / fmaxf((float)(e - s), 1.f);
    acc.x *= inv; acc.y *= inv;
    *(float2*)&out_item[(size_t)gw * D + 2 * lane] = acc;
}

// ---------------- launch ----------------
extern "C" void kernel_launch(void* const* d_in, const int* in_sizes, int n_in,
                              void* d_out, int out_size) {
    const float* ent   = (const float*)d_in[0];
    const float* user  = (const float*)d_in[1];
    const float* ucf   = (const float*)d_in[2];
    const float* icf   = (const float*)d_in[3];
    const float* relw  = (const float*)d_in[4];
    const float* W1    = (const float*)d_in[5];
    const float* b1    = (const float*)d_in[6];
    const float* W2    = (const float*)d_in[7];
    const float* b2    = (const float*)d_in[8];
    const int*   eidx  = (const int*)d_in[9];     // [2, N_EDGES]
    const int*   etype = (const int*)d_in[10];
    const int*   imat  = (const int*)d_in[11];    // [N_INTER, 2]

    float* out      = (float*)d_out;
    float* out_ent  = out;                                   // 100000*64
    float* out_u    = out_ent + (size_t)N_ENT * D;           // 50000*64
    float* out_ucf  = out_u   + (size_t)N_USERS * D;         // 50000*64
    float* out_item = out_ucf + (size_t)N_USERS * D;         // 30000*64
    float* out_mask = out_item + (size_t)N_ITEMS * D;        // 1000000

    const int T = 256;
    // --- sort 1: edges by head ---
    zero_bins_kernel<<<(N_ENT + T - 1) / T, T>>>(N_ENT);
    hist_kernel<<<(N_EDGES + T - 1) / T, T>>>(eidx, N_EDGES, 1);
    scan_kernel<<<1, 1024>>>(N_ENT, 0);
    scatter_edges_kernel<<<(N_EDGES + T - 1) / T, T>>>(eidx, eidx + N_EDGES, etype, N_EDGES);

    // --- sort 2: interactions by row (user) ---
    zero_bins_kernel<<<(N_USERS + T - 1) / T, T>>>(N_USERS);
    hist_kernel<<<(N_INTER + T - 1) / T, T>>>(imat, N_INTER, 2);
    scan_kernel<<<1, 1024>>>(N_USERS, 1);
    scatter_inter_row_kernel<<<(N_INTER + T - 1) / T, T>>>(imat, N_INTER);

    // --- sort 3: interactions by col (item) ---
    zero_bins_kernel<<<(N_ITEMS + T - 1) / T, T>>>(N_ITEMS);
    hist_kernel<<<(N_INTER + T - 1) / T, T>>>(imat + 1, N_INTER, 2);
    scan_kernel<<<1, 1024>>>(N_ITEMS, 2);
    scatter_inter_col_kernel<<<(N_INTER + T - 1) / T, T>>>(imat, N_INTER);

    // --- KG aggregation (also builds g_wkg) ---
    entity_kernel<<<N_ENT / 8, T>>>(ent, relw, W1, b1, W2, b2, out_ent);

    // --- 3 CF iterations ---
    iter_kernel<<<N_USERS * 32 / T, T>>>(user, ucf, 0, nullptr, nullptr, 0,
                                         ent, icf, nullptr, 0);
    iter_kernel<<<N_USERS * 32 / T, T>>>(nullptr, nullptr, 1, nullptr, nullptr, 1,
                                         ent, icf, nullptr, 0);
    iter_kernel<<<N_USERS * 32 / T, T>>>(nullptr, nullptr, 2, out_u, out_ucf, 2,
                                         ent, icf, out_mask, 1);

    // --- item_agg ---
    item_kernel<<<N_ITEMS * 32 / T, T>>>(ucf, out_item);
}

// round 2
// speedup vs baseline: 1.3630x; 1.3630x over previous
#include <cuda_runtime.h>

#define N_USERS   50000
#define N_ITEMS   30000
#define N_ENT     100000
#define N_REL     50
#define N_EDGES   1500000
#define N_INTER   1000000
#define D         64
#define GAMMA_F   0.1f

// ---------------- static device scratch ----------------
__device__ int   g_bins_e[N_ENT];
__device__ int   g_bins_r[N_USERS];
__device__ int   g_bins_c[N_ITEMS];
__device__ int   g_cur_e[N_ENT];
__device__ int   g_cur_r[N_USERS];
__device__ int   g_cur_c[N_ITEMS];
__device__ int   g_eoff[N_ENT + 1];
__device__ int   g_roff[N_USERS + 1];
__device__ int   g_coff[N_ITEMS + 1];
__device__ int   g_stail[N_EDGES];
__device__ int   g_srel[N_EDGES];
__device__ int   g_rcol[N_INTER];
__device__ int   g_ridx[N_INTER];
__device__ int   g_crow[N_INTER];
__device__ float g_wkg[N_ITEMS * D];   // rel_mean[:N_ITEMS] * entity_emb[:N_ITEMS]
__device__ float g_cu[N_INTER];        // pass1: exp(sigmoid(d1)); mid: pn*m
__device__ float g_cc[N_INTER];

__device__ __forceinline__ float fsigmoid(float x) {
    return __fdividef(1.f, 1.f + __expf(-x));
}

// ---------------- fused setup kernels ----------------
__global__ void zero3_kernel() {
    int i = blockIdx.x * blockDim.x + threadIdx.x;
    if (i < N_ENT)   g_bins_e[i] = 0;
    if (i < N_USERS) g_bins_r[i] = 0;
    if (i < N_ITEMS) g_bins_c[i] = 0;
}

__global__ void hist3_kernel(const int* __restrict__ head,
                             const int* __restrict__ imat) {
    int i = blockIdx.x * blockDim.x + threadIdx.x;
    if (i < N_EDGES) atomicAdd(&g_bins_e[head[i]], 1);
    if (i < N_INTER) {
        atomicAdd(&g_bins_r[imat[(size_t)2 * i]], 1);
        atomicAdd(&g_bins_c[imat[(size_t)2 * i + 1]], 1);
    }
}

// 3 blocks: block b scans its structure (exclusive scan + cursor copy)
__global__ void scan3_kernel() {
    int which = blockIdx.x;
    int n = (which == 0) ? N_ENT : (which == 1) ? N_USERS : N_ITEMS;
    int* bins = (which == 0) ? g_bins_e : (which == 1) ? g_bins_r : g_bins_c;
    int* offs = (which == 0) ? g_eoff   : (which == 1) ? g_roff   : g_coff;
    int* cur  = (which == 0) ? g_cur_e  : (which == 1) ? g_cur_r  : g_cur_c;
    __shared__ int warpsum[32];
    __shared__ int s_carry;
    int tid = threadIdx.x, lane = tid & 31, wid = tid >> 5;
    if (tid == 0) s_carry = 0;
    __syncthreads();
    for (int base = 0; base < n; base += 1024) {
        int i = base + tid;
        int v = (i < n) ? bins[i] : 0;
        int x = v;
        #pragma unroll
        for (int o = 1; o < 32; o <<= 1) {
            int t = __shfl_up_sync(0xffffffffu, x, o);
            if (lane >= o) x += t;
        }
        if (lane == 31) warpsum[wid] = x;
        __syncthreads();
        if (wid == 0) {
            int w = warpsum[lane];
            #pragma unroll
            for (int o = 1; o < 32; o <<= 1) {
                int t = __shfl_up_sync(0xffffffffu, w, o);
                if (lane >= o) w += t;
            }
            warpsum[lane] = w;
        }
        __syncthreads();
        int incl = x + (wid ? warpsum[wid - 1] : 0);
        int carry = s_carry;
        if (i < n) {
            int off = carry + incl - v;
            offs[i] = off;
            cur[i]  = off;
        }
        __syncthreads();
        if (tid == 1023) s_carry = carry + incl;
        __syncthreads();
    }
    if (threadIdx.x == 0) offs[n] = s_carry;
}

__global__ void scatter3_kernel(const int* __restrict__ head,
                                const int* __restrict__ tail,
                                const int* __restrict__ etype,
                                const int* __restrict__ imat) {
    int i = blockIdx.x * blockDim.x + threadIdx.x;
    if (i < N_EDGES) {
        int h = head[i];
        int pos = atomicAdd(&g_cur_e[h], 1);
        g_stail[pos] = tail[i];
        g_srel[pos]  = etype[i];
    }
    if (i < N_INTER) {
        int r = imat[(size_t)2 * i];
        int c = imat[(size_t)2 * i + 1];
        int pr = atomicAdd(&g_cur_r[r], 1);
        g_rcol[pr] = c;
        g_ridx[pr] = i;
        int pc = atomicAdd(&g_cur_c[c], 1);
        g_crow[pc] = r;
    }
}

// ---------------- KG aggregation: warp per entity, fused matmuls ----------------
__global__ void __launch_bounds__(256) entity_kernel(
    const float* __restrict__ ent, const float* __restrict__ relw,
    const float* __restrict__ W1, const float* __restrict__ b1,
    const float* __restrict__ W2, const float* __restrict__ b2,
    float* __restrict__ out_agg)
{
    __shared__ float sW1t[D * D];
    __shared__ float sW2t[D * D];
    __shared__ float sRel[N_REL * D];
    __shared__ float sMean[8][D];
    int tid = threadIdx.x;
    for (int i = tid; i < D * D; i += 256) {
        int d = i / D, k = i % D;
        sW1t[k * D + d] = W1[i];
        sW2t[k * D + d] = W2[i];
    }
    for (int i = tid; i < N_REL * D; i += 256) sRel[i] = relw[i];
    __syncthreads();

    int warp = tid >> 5, lane = tid & 31;
    int h = blockIdx.x * 8 + warp;
    if (h >= N_ENT) return;
    int s = g_eoff[h], e = g_eoff[h + 1];
    bool head_item = (h < N_ITEMS);

    float2 a1 = make_float2(0.f, 0.f), a2 = a1, ar = a1;
    int c1 = 0, c2 = 0;
    #pragma unroll 4
    for (int j = s; j < e; j++) {
        int t = g_stail[j];
        int r = g_srel[j];
        float2 te = *(const float2*)&ent[(size_t)t * D + 2 * lane];
        float2 re = *(const float2*)&sRel[r * D + 2 * lane];
        ar.x += re.x; ar.y += re.y;
        bool cross = head_item ^ (t < N_ITEMS);
        if (cross) { a1.x += te.x * re.x; a1.y += te.y * re.y; c1++; }
        else       { a2.x += te.x + re.x; a2.y += te.y + re.y; c2++; }
    }
    float inv1 = 1.f / fmaxf((float)c1, 1.f);
    float inv2 = 1.f / fmaxf((float)c2, 1.f);
    float invr = 1.f / fmaxf((float)(e - s), 1.f);
    a1.x *= inv1; a1.y *= inv1;
    a2.x *= inv2; a2.y *= inv2;
    ar.x *= invr; ar.y *= invr;

    if (head_item) {
        float2 kg = *(const float2*)&ent[(size_t)h * D + 2 * lane];
        float2 w  = make_float2(ar.x * kg.x, ar.y * kg.y);
        *(float2*)&g_wkg[(size_t)h * D + 2 * lane] = w;
    }

    sMean[warp][2 * lane] = a1.x;
    sMean[warp][2 * lane + 1] = a1.y;
    __syncwarp();
    float o0 = b1[2 * lane], o1 = b1[2 * lane + 1];
    #pragma unroll 8
    for (int k = 0; k < D; k++) {
        float m = sMean[warp][k];
        float2 w = *(const float2*)&sW1t[k * D + 2 * lane];
        o0 += m * w.x; o1 += m * w.y;
    }
    o0 = (o0 >= 0.f ? o0 : 0.01f * o0) * 0.5f;
    o1 = (o1 >= 0.f ? o1 : 0.01f * o1) * 0.5f;
    __syncwarp();

    sMean[warp][2 * lane] = a2.x;
    sMean[warp][2 * lane + 1] = a2.y;
    __syncwarp();
    float p0 = b2[2 * lane], p1 = b2[2 * lane + 1];
    #pragma unroll 8
    for (int k = 0; k < D; k++) {
        float m = sMean[warp][k];
        float2 w = *(const float2*)&sW2t[k * D + 2 * lane];
        p0 += m * w.x; p1 += m * w.y;
    }
    p0 = (p0 >= 0.f ? p0 : 0.01f * p0) * 0.5f;
    p1 = (p1 >= 0.f ? p1 : 0.01f * p1) * 0.5f;

    float2 o = make_float2(o0 + p0, o1 + p1);
    *(float2*)&out_agg[(size_t)h * D + 2 * lane] = o;
}

// ---------------- fused 3-iteration CF attention: warp per user ----------------
__global__ void __launch_bounds__(256) iter3_kernel(
    const float* __restrict__ user, const float* __restrict__ ucf0,
    const float* __restrict__ ent,  const float* __restrict__ icf,
    float* __restrict__ out_u, float* __restrict__ out_ucf,
    float* __restrict__ out_mask)
{
    int gw = (blockIdx.x * 256 + threadIdx.x) >> 5;
    int lane = threadIdx.x & 31;
    if (gw >= N_USERS) return;
    int s = g_roff[gw], e = g_roff[gw + 1];

    float2 u = *(const float2*)&user[(size_t)gw * D + 2 * lane];
    float2 c = *(const float2*)&ucf0[(size_t)gw * D + 2 * lane];

    #pragma unroll 1
    for (int it = 0; it < 3; it++) {
        // ---- pass 1: dots + softmax numerators ----
        float z = 0.f, zc = 0.f;
        int j = s;
        for (; j + 4 <= e; j += 4) {
            int c0 = g_rcol[j], c1 = g_rcol[j + 1], c2 = g_rcol[j + 2], c3 = g_rcol[j + 3];
            float2 w0 = *(const float2*)&g_wkg[(size_t)c0 * D + 2 * lane];
            float2 w1 = *(const float2*)&g_wkg[(size_t)c1 * D + 2 * lane];
            float2 w2 = *(const float2*)&g_wkg[(size_t)c2 * D + 2 * lane];
            float2 w3 = *(const float2*)&g_wkg[(size_t)c3 * D + 2 * lane];
            float2 v0 = *(const float2*)&icf[(size_t)c0 * D + 2 * lane];
            float2 v1 = *(const float2*)&icf[(size_t)c1 * D + 2 * lane];
            float2 v2 = *(const float2*)&icf[(size_t)c2 * D + 2 * lane];
            float2 v3 = *(const float2*)&icf[(size_t)c3 * D + 2 * lane];
            float d10 = u.x * w0.x + u.y * w0.y;
            float d11 = u.x * w1.x + u.y * w1.y;
            float d12 = u.x * w2.x + u.y * w2.y;
            float d13 = u.x * w3.x + u.y * w3.y;
            float d20 = c.x * v0.x + c.y * v0.y;
            float d21 = c.x * v1.x + c.y * v1.y;
            float d22 = c.x * v2.x + c.y * v2.y;
            float d23 = c.x * v3.x + c.y * v3.y;
            #pragma unroll
            for (int o = 16; o; o >>= 1) {
                d10 += __shfl_xor_sync(0xffffffffu, d10, o);
                d11 += __shfl_xor_sync(0xffffffffu, d11, o);
                d12 += __shfl_xor_sync(0xffffffffu, d12, o);
                d13 += __shfl_xor_sync(0xffffffffu, d13, o);
                d20 += __shfl_xor_sync(0xffffffffu, d20, o);
                d21 += __shfl_xor_sync(0xffffffffu, d21, o);
                d22 += __shfl_xor_sync(0xffffffffu, d22, o);
                d23 += __shfl_xor_sync(0xffffffffu, d23, o);
            }
            int sl = lane & 3;
            float myd1 = (sl & 2) ? ((sl & 1) ? d13 : d12) : ((sl & 1) ? d11 : d10);
            float myd2 = (sl & 2) ? ((sl & 1) ? d23 : d22) : ((sl & 1) ? d21 : d20);
            float ep = __expf(fsigmoid(myd1));
            float eq = __expf(fsigmoid(myd2));
            if (lane < 4) {
                z += ep; zc += eq;
                g_cu[j + lane] = ep;
                g_cc[j + lane] = eq;
            }
        }
        for (; j < e; j++) {
            int col = g_rcol[j];
            float2 w = *(const float2*)&g_wkg[(size_t)col * D + 2 * lane];
            float2 v = *(const float2*)&icf[(size_t)col * D + 2 * lane];
            float d1 = u.x * w.x + u.y * w.y;
            float d2 = c.x * v.x + c.y * v.y;
            #pragma unroll
            for (int o = 16; o; o >>= 1) {
                d1 += __shfl_xor_sync(0xffffffffu, d1, o);
                d2 += __shfl_xor_sync(0xffffffffu, d2, o);
            }
            float ep = __expf(fsigmoid(d1));
            float eq = __expf(fsigmoid(d2));
            if (lane == 0) {
                z += ep; zc += eq;
                g_cu[j] = ep;
                g_cc[j] = eq;
            }
        }
        __syncwarp();
        // combine partial z (lanes 0-3 + tail in lane 0)
        #pragma unroll
        for (int o = 16; o; o >>= 1) {
            z  += __shfl_xor_sync(0xffffffffu, z, o);
            zc += __shfl_xor_sync(0xffffffffu, zc, o);
        }
        float iz  = (z  > 0.f) ? __fdividef(1.f, z)  : 0.f;
        float izc = (zc > 0.f) ? __fdividef(1.f, zc) : 0.f;

        // ---- mid loop: lane-parallel coefficients + mask ----
        for (int jj = s + lane; jj < e; jj += 32) {
            float pn = g_cu[jj] * iz;
            float qn = g_cc[jj] * izc;
            float sp = fsigmoid(pn);
            float sq = fsigmoid(qn);
            float m  = (fabsf(sp - sq) < GAMMA_F) ? 1.f : 0.f;
            if (it == 2) out_mask[g_ridx[jj]] = m;
            g_cu[jj] = pn * m;
            g_cc[jj] = qn * m;
        }
        __syncwarp();

        // ---- pass 2: weighted sums ----
        float2 au = make_float2(0.f, 0.f), ac = make_float2(0.f, 0.f);
        #pragma unroll 2
        for (int j2 = s; j2 < e; j2++) {
            int col = g_rcol[j2];
            float cu = g_cu[j2], cc = g_cc[j2];
            float2 kg = *(const float2*)&ent[(size_t)col * D + 2 * lane];
            float2 v  = *(const float2*)&icf[(size_t)col * D + 2 * lane];
            au.x += cu * kg.x; au.y += cu * kg.y;
            ac.x += cc * v.x;  ac.y += cc * v.y;
        }

        if (it < 2) {
            float su = au.x * au.x + au.y * au.y;
            float sc = ac.x * ac.x + ac.y * ac.y;
            #pragma unroll
            for (int o = 16; o; o >>= 1) {
                su += __shfl_xor_sync(0xffffffffu, su, o);
                sc += __shfl_xor_sync(0xffffffffu, sc, o);
            }
            float inu = __fdividef(1.f, fmaxf(sqrtf(su), 1e-12f));
            float inc = __fdividef(1.f, fmaxf(sqrtf(sc), 1e-12f));
            u.x = au.x * inu; u.y = au.y * inu;
            c.x = ac.x * inc; c.y = ac.y * inc;
        } else {
            *(float2*)&out_u[(size_t)gw * D + 2 * lane]   = au;
            *(float2*)&out_ucf[(size_t)gw * D + 2 * lane] = ac;
        }
        __syncwarp();
    }
}

// ---------------- item_agg: warp per item ----------------
__global__ void __launch_bounds__(256) item_kernel(
    const float* __restrict__ ucf, float* __restrict__ out_item)
{
    int gw = (blockIdx.x * 256 + threadIdx.x) >> 5;
    int lane = threadIdx.x & 31;
    if (gw >= N_ITEMS) return;
    int s = g_coff[gw], e = g_coff[gw + 1];
    float2 acc = make_float2(0.f, 0.f);
    #pragma unroll 4
    for (int j = s; j < e; j++) {
        int r = g_crow[j];
        float2 v = *(const float2*)&ucf[(size_t)r * D + 2 * lane];
        acc.x += v.x; acc.y += v.y;
    }
    float inv = 1.f / fmaxf((float)(e - s), 1.f);
    acc.x *= inv; acc.y *= inv;
    *(float2*)&out_item[(size_t)gw * D + 2 * lane] = acc;
}

// ---------------- launch ----------------
extern "C" void kernel_launch(void* const* d_in, const int* in_sizes, int n_in,
                              void* d_out, int out_size) {
    const float* ent   = (const float*)d_in[0];
    const float* user  = (const float*)d_in[1];
    const float* ucf   = (const float*)d_in[2];
    const float* icf   = (const float*)d_in[3];
    const float* relw  = (const float*)d_in[4];
    const float* W1    = (const float*)d_in[5];
    const float* b1    = (const float*)d_in[6];
    const float* W2    = (const float*)d_in[7];
    const float* b2    = (const float*)d_in[8];
    const int*   eidx  = (const int*)d_in[9];     // [2, N_EDGES]
    const int*   etype = (const int*)d_in[10];
    const int*   imat  = (const int*)d_in[11];    // [N_INTER, 2]

    float* out      = (float*)d_out;
    float* out_ent  = out;
    float* out_u    = out_ent + (size_t)N_ENT * D;
    float* out_ucf  = out_u   + (size_t)N_USERS * D;
    float* out_item = out_ucf + (size_t)N_USERS * D;
    float* out_mask = out_item + (size_t)N_ITEMS * D;

    const int T = 256;
    zero3_kernel<<<(N_ENT + T - 1) / T, T>>>();
    hist3_kernel<<<(N_EDGES + T - 1) / T, T>>>(eidx, imat);
    scan3_kernel<<<3, 1024>>>();
    scatter3_kernel<<<(N_EDGES + T - 1) / T, T>>>(eidx, eidx + N_EDGES, etype, imat);

    entity_kernel<<<N_ENT / 8, T>>>(ent, relw, W1, b1, W2, b2, out_ent);

    iter3_kernel<<<N_USERS * 32 / T, T>>>(user, ucf, ent, icf,
                                          out_u, out_ucf, out_mask);

    item_kernel<<<N_ITEMS * 32 / T, T>>>(ucf, out_item);
}

// round 3
// speedup vs baseline: 2.5229x; 1.8510x over previous
#include <cuda_runtime.h>

#define N_USERS   50000
#define N_ITEMS   30000
#define N_ENT     100000
#define N_REL     50
#define N_EDGES   1500000
#define N_INTER   1000000
#define D         64
#define GAMMA_F   0.1f

// scan partition: 2048 elems per block
#define PB0 49   // ceil(N_ENT/2048)
#define PB1 25   // ceil(N_USERS/2048)
#define PB2 15   // ceil(N_ITEMS/2048)
#define PBT (PB0 + PB1 + PB2)

// ---------------- static device scratch ----------------
__device__ int   g_bins_e[N_ENT];
__device__ int   g_bins_r[N_USERS];
__device__ int   g_bins_c[N_ITEMS];
__device__ int   g_cur_e[N_ENT];
__device__ int   g_cur_r[N_USERS];
__device__ int   g_cur_c[N_ITEMS];
__device__ int   g_eoff[N_ENT + 1];
__device__ int   g_roff[N_USERS + 1];
__device__ int   g_coff[N_ITEMS + 1];
__device__ int   g_part[PBT];
__device__ int2  g_te[N_EDGES];        // (tail, rel)
__device__ int2  g_rc[N_INTER];        // (col, orig idx)
__device__ int   g_crow[N_INTER];
__device__ float g_W1t[D * D];         // transposed [k][d]
__device__ float g_W2t[D * D];
__device__ float g_wkg[N_ITEMS * D];
__device__ float g_cu[N_INTER];
__device__ float g_cc[N_INTER];

__device__ __forceinline__ float fsigmoid(float x) {
    return __fdividef(1.f, 1.f + __expf(-x));
}

// ---------------- setup: zero bins + transpose W ----------------
__global__ void zero3_kernel(const float* __restrict__ W1, const float* __restrict__ W2) {
    int i = blockIdx.x * blockDim.x + threadIdx.x;
    if (i < N_ENT)   g_bins_e[i] = 0;
    if (i < N_USERS) g_bins_r[i] = 0;
    if (i < N_ITEMS) g_bins_c[i] = 0;
    if (i < D * D) {
        int d = i >> 6, k = i & 63;
        g_W1t[(k << 6) + d] = W1[i];
        g_W2t[(k << 6) + d] = W2[i];
    }
}

__global__ void hist3_kernel(const int* __restrict__ head,
                             const int* __restrict__ imat) {
    int i = blockIdx.x * blockDim.x + threadIdx.x;
    if (i < N_EDGES) atomicAdd(&g_bins_e[head[i]], 1);
    if (i < N_INTER) {
        atomicAdd(&g_bins_r[imat[(size_t)2 * i]], 1);
        atomicAdd(&g_bins_c[imat[(size_t)2 * i + 1]], 1);
    }
}

// ---------------- 3-phase multi-block scan ----------------
__device__ __forceinline__ void scan_map(int b, int& which, int& lb) {
    which = (b < PB0) ? 0 : (b < PB0 + PB1) ? 1 : 2;
    lb = b - ((which == 0) ? 0 : (which == 1) ? PB0 : PB0 + PB1);
}

__global__ void __launch_bounds__(256) scanA_kernel() {
    int which, lb;
    scan_map(blockIdx.x, which, lb);
    int n = (which == 0) ? N_ENT : (which == 1) ? N_USERS : N_ITEMS;
    const int* bins = (which == 0) ? g_bins_e : (which == 1) ? g_bins_r : g_bins_c;
    int base = lb * 2048;
    int sum = 0;
    for (int i = threadIdx.x; i < 2048; i += 256) {
        int idx = base + i;
        sum += (idx < n) ? bins[idx] : 0;
    }
    #pragma unroll
    for (int o = 16; o; o >>= 1) sum += __shfl_xor_sync(0xffffffffu, sum, o);
    __shared__ int ws[8];
    int lane = threadIdx.x & 31, wid = threadIdx.x >> 5;
    if (lane == 0) ws[wid] = sum;
    __syncthreads();
    if (threadIdx.x == 0) {
        int t = 0;
        #pragma unroll
        for (int i = 0; i < 8; i++) t += ws[i];
        g_part[blockIdx.x] = t;
    }
}

__global__ void scanB_kernel() {
    int w = threadIdx.x >> 5, lane = threadIdx.x & 31;
    if (w >= 3) return;
    int nb   = (w == 0) ? PB0 : (w == 1) ? PB1 : PB2;
    int base = (w == 0) ? 0   : (w == 1) ? PB0 : PB0 + PB1;
    int carry = 0;
    for (int b0 = 0; b0 < nb; b0 += 32) {
        int i = b0 + lane;
        int v = (i < nb) ? g_part[base + i] : 0;
        int x = v;
        #pragma unroll
        for (int o = 1; o < 32; o <<= 1) {
            int t = __shfl_up_sync(0xffffffffu, x, o);
            if (lane >= o) x += t;
        }
        if (i < nb) g_part[base + i] = carry + x - v;
        carry += __shfl_sync(0xffffffffu, x, 31);
    }
    if (lane == 0) {
        if (w == 0) g_eoff[N_ENT] = carry;
        else if (w == 1) g_roff[N_USERS] = carry;
        else g_coff[N_ITEMS] = carry;
    }
}

__global__ void __launch_bounds__(256) scanC_kernel() {
    int which, lb;
    scan_map(blockIdx.x, which, lb);
    int n = (which == 0) ? N_ENT : (which == 1) ? N_USERS : N_ITEMS;
    const int* bins = (which == 0) ? g_bins_e : (which == 1) ? g_bins_r : g_bins_c;
    int* offs = (which == 0) ? g_eoff : (which == 1) ? g_roff : g_coff;
    int* cur  = (which == 0) ? g_cur_e : (which == 1) ? g_cur_r : g_cur_c;
    int base = lb * 2048;
    int lane = threadIdx.x & 31, wid = threadIdx.x >> 5;

    int vals[8];
    int tsum = 0;
    #pragma unroll
    for (int k = 0; k < 8; k++) {
        int idx = base + threadIdx.x * 8 + k;
        vals[k] = (idx < n) ? bins[idx] : 0;
        tsum += vals[k];
    }
    int x = tsum;
    #pragma unroll
    for (int o = 1; o < 32; o <<= 1) {
        int t = __shfl_up_sync(0xffffffffu, x, o);
        if (lane >= o) x += t;
    }
    __shared__ int ws[8];
    if (lane == 31) ws[wid] = x;
    __syncthreads();
    int wpref = 0;
    for (int i = 0; i < wid; i++) wpref += ws[i];
    int acc = g_part[blockIdx.x] + wpref + x - tsum;
    #pragma unroll
    for (int k = 0; k < 8; k++) {
        int idx = base + threadIdx.x * 8 + k;
        if (idx < n) { offs[idx] = acc; cur[idx] = acc; }
        acc += vals[k];
    }
}

__global__ void scatter3_kernel(const int* __restrict__ head,
                                const int* __restrict__ tail,
                                const int* __restrict__ etype,
                                const int* __restrict__ imat) {
    int i = blockIdx.x * blockDim.x + threadIdx.x;
    if (i < N_EDGES) {
        int h = head[i];
        int pos = atomicAdd(&g_cur_e[h], 1);
        g_te[pos] = make_int2(tail[i], etype[i]);
    }
    if (i < N_INTER) {
        int r = imat[(size_t)2 * i];
        int c = imat[(size_t)2 * i + 1];
        int pr = atomicAdd(&g_cur_r[r], 1);
        g_rc[pr] = make_int2(c, i);
        int pc = atomicAdd(&g_cur_c[c], 1);
        g_crow[pc] = r;
    }
}

// ---------------- KG aggregation: 2 entities per warp, float4 lanes ----------------
__global__ void __launch_bounds__(256) entity_kernel(
    const float* __restrict__ ent, const float* __restrict__ relw,
    const float* __restrict__ b1, const float* __restrict__ b2,
    float* __restrict__ out_agg)
{
    __shared__ float sRel[N_REL * D];
    __shared__ float sMA[8][2][D];
    __shared__ float sMB[8][2][D];
    int tid = threadIdx.x;
    for (int i = tid; i < N_REL * D; i += 256) sRel[i] = relw[i];
    __syncthreads();

    int warp = tid >> 5, lane = tid & 31, hl = lane >> 4, q = lane & 15;
    int h = blockIdx.x * 16 + warp * 2 + hl;     // 6250*16 = 100000 exact
    int s = g_eoff[h], e = g_eoff[h + 1];
    bool head_item = (h < N_ITEMS);

    float4 a1 = make_float4(0.f, 0.f, 0.f, 0.f), a2 = a1, ar = a1;
    int c1 = 0, c2 = 0;
    for (int j = s; j < e; j++) {
        int2 tr = g_te[j];
        float4 te = *(const float4*)&ent[(size_t)tr.x * D + q * 4];
        float4 re = *(const float4*)&sRel[tr.y * D + q * 4];
        ar.x += re.x; ar.y += re.y; ar.z += re.z; ar.w += re.w;
        bool cross = head_item ^ (tr.x < N_ITEMS);
        if (cross) {
            a1.x += te.x * re.x; a1.y += te.y * re.y;
            a1.z += te.z * re.z; a1.w += te.w * re.w; c1++;
        } else {
            a2.x += te.x + re.x; a2.y += te.y + re.y;
            a2.z += te.z + re.z; a2.w += te.w + re.w; c2++;
        }
    }
    float inv1 = 1.f / fmaxf((float)c1, 1.f);
    float inv2 = 1.f / fmaxf((float)c2, 1.f);
    float invr = 1.f / fmaxf((float)(e - s), 1.f);

    if (head_item) {
        float4 kg = *(const float4*)&ent[(size_t)h * D + q * 4];
        float4 w = make_float4(ar.x * invr * kg.x, ar.y * invr * kg.y,
                               ar.z * invr * kg.z, ar.w * invr * kg.w);
        *(float4*)&g_wkg[(size_t)h * D + q * 4] = w;
    }

    *(float4*)&sMA[warp][hl][q * 4] = make_float4(a1.x * inv1, a1.y * inv1, a1.z * inv1, a1.w * inv1);
    *(float4*)&sMB[warp][hl][q * 4] = make_float4(a2.x * inv2, a2.y * inv2, a2.z * inv2, a2.w * inv2);
    __syncwarp();

    float4 o = *(const float4*)&b1[q * 4];
    float4 p = *(const float4*)&b2[q * 4];
    #pragma unroll 8
    for (int k = 0; k < D; k++) {
        float m1 = sMA[warp][hl][k];
        float m2 = sMB[warp][hl][k];
        float4 w1 = *(const float4*)&g_W1t[k * D + q * 4];
        float4 w2 = *(const float4*)&g_W2t[k * D + q * 4];
        o.x += m1 * w1.x; o.y += m1 * w1.y; o.z += m1 * w1.z; o.w += m1 * w1.w;
        p.x += m2 * w2.x; p.y += m2 * w2.y; p.z += m2 * w2.z; p.w += m2 * w2.w;
    }
    float4 r;
    r.x = (o.x >= 0.f ? o.x : 0.01f * o.x) * 0.5f + (p.x >= 0.f ? p.x : 0.01f * p.x) * 0.5f;
    r.y = (o.y >= 0.f ? o.y : 0.01f * o.y) * 0.5f + (p.y >= 0.f ? p.y : 0.01f * p.y) * 0.5f;
    r.z = (o.z >= 0.f ? o.z : 0.01f * o.z) * 0.5f + (p.z >= 0.f ? p.z : 0.01f * p.z) * 0.5f;
    r.w = (o.w >= 0.f ? o.w : 0.01f * o.w) * 0.5f + (p.w >= 0.f ? p.w : 0.01f * p.w) * 0.5f;
    *(float4*)&out_agg[(size_t)h * D + q * 4] = r;
}

// ---------------- fused: 3 CF iterations (warp/user) + item_agg (warp/item) ----------------
#define UBLK 6250   // 50000 users / 8 warps
#define IBLK 3750   // 30000 items / 8 warps

__global__ void __launch_bounds__(256) iter3_item_kernel(
    const float* __restrict__ user, const float* __restrict__ ucf0,
    const float* __restrict__ ent,  const float* __restrict__ icf,
    float* __restrict__ out_u, float* __restrict__ out_ucf,
    float* __restrict__ out_mask, float* __restrict__ out_item)
{
    int warp = threadIdx.x >> 5, lane = threadIdx.x & 31;
    int hl = lane >> 4, q = lane & 15;

    if (blockIdx.x >= UBLK) {
        // -------- item_agg path --------
        int it = (blockIdx.x - UBLK) * 8 + warp;   // 3750*8 = 30000 exact
        int s = g_coff[it], e = g_coff[it + 1];
        float4 acc = make_float4(0.f, 0.f, 0.f, 0.f);
        int j = s;
        for (; j + 2 <= e; j += 2) {
            int r = g_crow[j + hl];
            float4 v = *(const float4*)&ucf0[(size_t)r * D + q * 4];
            acc.x += v.x; acc.y += v.y; acc.z += v.z; acc.w += v.w;
        }
        if (j < e && hl == 0) {
            int r = g_crow[j];
            float4 v = *(const float4*)&ucf0[(size_t)r * D + q * 4];
            acc.x += v.x; acc.y += v.y; acc.z += v.z; acc.w += v.w;
        }
        acc.x += __shfl_xor_sync(0xffffffffu, acc.x, 16);
        acc.y += __shfl_xor_sync(0xffffffffu, acc.y, 16);
        acc.z += __shfl_xor_sync(0xffffffffu, acc.z, 16);
        acc.w += __shfl_xor_sync(0xffffffffu, acc.w, 16);
        if (hl == 0) {
            float inv = 1.f / fmaxf((float)(e - s), 1.f);
            float4 r = make_float4(acc.x * inv, acc.y * inv, acc.z * inv, acc.w * inv);
            *(float4*)&out_item[(size_t)it * D + q * 4] = r;
        }
        return;
    }

    // -------- user path: 3 fused iterations --------
    int gw = blockIdx.x * 8 + warp;   // 6250*8 = 50000 exact
    int s = g_roff[gw], e = g_roff[gw + 1];

    float4 u = *(const float4*)&user[(size_t)gw * D + q * 4];
    float4 c = *(const float4*)&ucf0[(size_t)gw * D + q * 4];

    #pragma unroll 1
    for (int it = 0; it < 3; it++) {
        // ---- pass 1: dots + softmax numerators ----
        float z = 0.f, zc = 0.f;
        int j = s;
        #pragma unroll 2
        for (; j + 2 <= e; j += 2) {
            int col = g_rc[j + hl].x;
            float4 w = *(const float4*)&g_wkg[(size_t)col * D + q * 4];
            float4 v = *(const float4*)&icf[(size_t)col * D + q * 4];
            float d1 = u.x * w.x + u.y * w.y + u.z * w.z + u.w * w.w;
            float d2 = c.x * v.x + c.y * v.y + c.z * v.z + c.w * v.w;
            #pragma unroll
            for (int o = 8; o; o >>= 1) {
                d1 += __shfl_xor_sync(0xffffffffu, d1, o);
                d2 += __shfl_xor_sync(0xffffffffu, d2, o);
            }
            if (q == 0) {
                float ep = __expf(fsigmoid(d1));
                float eq = __expf(fsigmoid(d2));
                z += ep; zc += eq;
                g_cu[j + hl] = ep;
                g_cc[j + hl] = eq;
            }
        }
        if (j < e) {
            int col = g_rc[j].x;
            float4 w = *(const float4*)&g_wkg[(size_t)col * D + q * 4];
            float4 v = *(const float4*)&icf[(size_t)col * D + q * 4];
            float d1 = u.x * w.x + u.y * w.y + u.z * w.z + u.w * w.w;
            float d2 = c.x * v.x + c.y * v.y + c.z * v.z + c.w * v.w;
            #pragma unroll
            for (int o = 8; o; o >>= 1) {
                d1 += __shfl_xor_sync(0xffffffffu, d1, o);
                d2 += __shfl_xor_sync(0xffffffffu, d2, o);
            }
            if (lane == 0) {
                float ep = __expf(fsigmoid(d1));
                float eq = __expf(fsigmoid(d2));
                z += ep; zc += eq;
                g_cu[j] = ep;
                g_cc[j] = eq;
            }
        }
        __syncwarp();
        #pragma unroll
        for (int o = 16; o; o >>= 1) {
            z  += __shfl_xor_sync(0xffffffffu, z, o);
            zc += __shfl_xor_sync(0xffffffffu, zc, o);
        }
        float iz  = (z  > 0.f) ? __fdividef(1.f, z)  : 0.f;
        float izc = (zc > 0.f) ? __fdividef(1.f, zc) : 0.f;

        // ---- mid: lane-parallel coefficients + mask ----
        for (int jj = s + lane; jj < e; jj += 32) {
            float pn = g_cu[jj] * iz;
            float qn = g_cc[jj] * izc;
            float m = (fabsf(fsigmoid(pn) - fsigmoid(qn)) < GAMMA_F) ? 1.f : 0.f;
            if (it == 2) out_mask[g_rc[jj].y] = m;
            g_cu[jj] = pn * m;
            g_cc[jj] = qn * m;
        }
        __syncwarp();

        // ---- pass 2: weighted sums ----
        float4 au = make_float4(0.f, 0.f, 0.f, 0.f), ac = au;
        j = s;
        #pragma unroll 2
        for (; j + 2 <= e; j += 2) {
            int jj = j + hl;
            int col = g_rc[jj].x;
            float cu = g_cu[jj], cc = g_cc[jj];
            float4 kg = *(const float4*)&ent[(size_t)col * D + q * 4];
            float4 v  = *(const float4*)&icf[(size_t)col * D + q * 4];
            au.x += cu * kg.x; au.y += cu * kg.y; au.z += cu * kg.z; au.w += cu * kg.w;
            ac.x += cc * v.x;  ac.y += cc * v.y;  ac.z += cc * v.z;  ac.w += cc * v.w;
        }
        if (j < e && hl == 0) {
            int col = g_rc[j].x;
            float cu = g_cu[j], cc = g_cc[j];
            float4 kg = *(const float4*)&ent[(size_t)col * D + q * 4];
            float4 v  = *(const float4*)&icf[(size_t)col * D + q * 4];
            au.x += cu * kg.x; au.y += cu * kg.y; au.z += cu * kg.z; au.w += cu * kg.w;
            ac.x += cc * v.x;  ac.y += cc * v.y;  ac.z += cc * v.z;  ac.w += cc * v.w;
        }
        au.x += __shfl_xor_sync(0xffffffffu, au.x, 16);
        au.y += __shfl_xor_sync(0xffffffffu, au.y, 16);
        au.z += __shfl_xor_sync(0xffffffffu, au.z, 16);
        au.w += __shfl_xor_sync(0xffffffffu, au.w, 16);
        ac.x += __shfl_xor_sync(0xffffffffu, ac.x, 16);
        ac.y += __shfl_xor_sync(0xffffffffu, ac.y, 16);
        ac.z += __shfl_xor_sync(0xffffffffu, ac.z, 16);
        ac.w += __shfl_xor_sync(0xffffffffu, ac.w, 16);

        if (it < 2) {
            float su = au.x * au.x + au.y * au.y + au.z * au.z + au.w * au.w;
            float sc = ac.x * ac.x + ac.y * ac.y + ac.z * ac.z + ac.w * ac.w;
            #pragma unroll
            for (int o = 8; o; o >>= 1) {
                su += __shfl_xor_sync(0xffffffffu, su, o);
                sc += __shfl_xor_sync(0xffffffffu, sc, o);
            }
            float inu = __fdividef(1.f, fmaxf(sqrtf(su), 1e-12f));
            float inc = __fdividef(1.f, fmaxf(sqrtf(sc), 1e-12f));
            u.x = au.x * inu; u.y = au.y * inu; u.z = au.z * inu; u.w = au.w * inu;
            c.x = ac.x * inc; c.y = ac.y * inc; c.z = ac.z * inc; c.w = ac.w * inc;
        } else if (hl == 0) {
            *(float4*)&out_u[(size_t)gw * D + q * 4]   = au;
            *(float4*)&out_ucf[(size_t)gw * D + q * 4] = ac;
        }
        __syncwarp();
    }
}

// ---------------- launch ----------------
extern "C" void kernel_launch(void* const* d_in, const int* in_sizes, int n_in,
                              void* d_out, int out_size) {
    const float* ent   = (const float*)d_in[0];
    const float* user  = (const float*)d_in[1];
    const float* ucf   = (const float*)d_in[2];
    const float* icf   = (const float*)d_in[3];
    const float* relw  = (const float*)d_in[4];
    const float* W1    = (const float*)d_in[5];
    const float* b1    = (const float*)d_in[6];
    const float* W2    = (const float*)d_in[7];
    const float* b2    = (const float*)d_in[8];
    const int*   eidx  = (const int*)d_in[9];     // [2, N_EDGES]
    const int*   etype = (const int*)d_in[10];
    const int*   imat  = (const int*)d_in[11];    // [N_INTER, 2]

    float* out      = (float*)d_out;
    float* out_ent  = out;
    float* out_u    = out_ent + (size_t)N_ENT * D;
    float* out_ucf  = out_u   + (size_t)N_USERS * D;
    float* out_item = out_ucf + (size_t)N_USERS * D;
    float* out_mask = out_item + (size_t)N_ITEMS * D;

    const int T = 256;
    zero3_kernel<<<(N_ENT + T - 1) / T, T>>>(W1, W2);
    hist3_kernel<<<(N_EDGES + T - 1) / T, T>>>(eidx, imat);
    scanA_kernel<<<PBT, T>>>();
    scanB_kernel<<<1, 128>>>();
    scanC_kernel<<<PBT, T>>>();
    scatter3_kernel<<<(N_EDGES + T - 1) / T, T>>>(eidx, eidx + N_EDGES, etype, imat);

    entity_kernel<<<N_ENT / 16, T>>>(ent, relw, b1, b2, out_ent);

    iter3_item_kernel<<<UBLK + IBLK, T>>>(user, ucf, ent, icf,
                                          out_u, out_ucf, out_mask, out_item);
}